// round 3
// baseline (speedup 1.0000x reference)
#include <cuda_runtime.h>
#include <math.h>

#define BATCH   4
#define LSEQ    4096
#define M_TOTAL (BATCH * LSEQ)   // 16384
#define DM      1024
#define EE      2048             // E
#define N1      (2 * EE)         // 4096
#define DSTATE  16
#define DCONV   4

// -------- scratch (device globals: allocation-free rule) --------
__device__ float g_xz[M_TOTAL * (size_t)N1];    // 256 MB  (x_proj | z)
__device__ float g_xconv[M_TOTAL * (size_t)EE]; // 128 MB
__device__ float g_u[M_TOTAL * DSTATE];         // 1 MB
__device__ float g_h[M_TOTAL * DSTATE];         // 1 MB
__device__ float g_gated[M_TOTAL * (size_t)EE]; // 128 MB

// ============================================================
// Classic 128x128x8 register-tiled SGEMM with bias epilogue.
// C[M,N] = A[M,K] @ B[K,N] + bias[N]
// M % 128 == 0, N % 128 == 0, K % 8 == 0 (all true here).
// ============================================================
template <int BM, int BN, int BK, int TM, int TN>
__global__ __launch_bounds__(256, 2) void sgemm_bias(
    const float* __restrict__ A, const float* __restrict__ B,
    const float* __restrict__ bias, float* __restrict__ C,
    int M, int N, int K)
{
    __shared__ float As[BK][BM];
    __shared__ float Bs[BK][BN];

    const int tid = threadIdx.x;           // 0..255
    const int bm = blockIdx.y * BM;
    const int bn = blockIdx.x * BN;

    // load mapping
    const int a_row = tid >> 1;            // 0..127
    const int a_col = (tid & 1) * 4;       // 0 or 4
    const int b_row = tid >> 5;            // 0..7
    const int b_col = (tid & 31) * 4;      // 0..124

    // compute mapping
    const int ty = tid >> 4;               // 0..15
    const int tx = tid & 15;               // 0..15

    const float* Ag = A + (size_t)(bm + a_row) * K + a_col;
    const float* Bg = B + (size_t)b_row * N + bn + b_col;

    float acc[TM][TN];
#pragma unroll
    for (int i = 0; i < TM; i++)
#pragma unroll
        for (int j = 0; j < TN; j++) acc[i][j] = 0.f;

    for (int k0 = 0; k0 < K; k0 += BK) {
        float4 av = *(const float4*)(Ag + k0);
        As[a_col + 0][a_row] = av.x;
        As[a_col + 1][a_row] = av.y;
        As[a_col + 2][a_row] = av.z;
        As[a_col + 3][a_row] = av.w;
        float4 bv = *(const float4*)(Bg + (size_t)k0 * N);
        *(float4*)&Bs[b_row][b_col] = bv;
        __syncthreads();

#pragma unroll
        for (int k = 0; k < BK; k++) {
            float ra[TM], rb[TN];
            *(float4*)(ra)     = *(const float4*)&As[k][ty * TM];
            *(float4*)(ra + 4) = *(const float4*)&As[k][ty * TM + 4];
            *(float4*)(rb)     = *(const float4*)&Bs[k][tx * TN];
            *(float4*)(rb + 4) = *(const float4*)&Bs[k][tx * TN + 4];
#pragma unroll
            for (int i = 0; i < TM; i++)
#pragma unroll
                for (int j = 0; j < TN; j++)
                    acc[i][j] = fmaf(ra[i], rb[j], acc[i][j]);
        }
        __syncthreads();
    }

    // epilogue: + bias, vectorized stores
#pragma unroll
    for (int i = 0; i < TM; i++) {
        const size_t row = (size_t)(bm + ty * TM + i);
#pragma unroll
        for (int j = 0; j < TN; j += 4) {
            const int col = bn + tx * TN + j;
            float4 v;
            v.x = acc[i][j + 0] + bias[col + 0];
            v.y = acc[i][j + 1] + bias[col + 1];
            v.z = acc[i][j + 2] + bias[col + 2];
            v.w = acc[i][j + 3] + bias[col + 3];
            *(float4*)(C + row * N + col) = v;
        }
    }
}

// ============================================================
// Causal depthwise conv1d, k=4, padding=3 (left), per channel.
// x_proj = g_xz[:, 0:EE].  out: g_xconv
// ============================================================
__global__ void conv_kernel(const float* __restrict__ cw,
                            const float* __restrict__ cb,
                            float* __restrict__ xconv)
{
    const int idx = blockIdx.x * blockDim.x + threadIdx.x; // over M_TOTAL*EE
    const int e = idx & (EE - 1);
    const int m = idx >> 11;               // /EE
    const int l = m & (LSEQ - 1);

    float acc = cb[e];
    const float w0 = cw[e * 4 + 0];
    const float w1 = cw[e * 4 + 1];
    const float w2 = cw[e * 4 + 2];
    const float w3 = cw[e * 4 + 3];
    // out[l] = sum_t w[t] * in[l + t - 3]
    if (l >= 3) acc += w0 * g_xz[(size_t)(m - 3) * N1 + e];
    if (l >= 2) acc += w1 * g_xz[(size_t)(m - 2) * N1 + e];
    if (l >= 1) acc += w2 * g_xz[(size_t)(m - 1) * N1 + e];
    acc += w3 * g_xz[(size_t)m * N1 + e];
    xconv[(size_t)m * EE + e] = acc;
}

// ============================================================
// u[m, s] = sum_e xconv[m,e] * A[e,s]   (N=16 skinny GEMM)
// block: 64 rows x 4 s-groups (float4 over s), 256 threads
// ============================================================
__global__ void u_kernel(const float* __restrict__ Amat, float* __restrict__ u)
{
    const int m = blockIdx.x * 64 + (threadIdx.x >> 2);
    const int sg = (threadIdx.x & 3) * 4;
    const float* xr = g_xconv + (size_t)m * EE;

    float4 acc = make_float4(0.f, 0.f, 0.f, 0.f);
#pragma unroll 4
    for (int e = 0; e < EE; e += 4) {
        float4 xv = *(const float4*)(xr + e);
        float4 a0 = *(const float4*)(Amat + (e + 0) * DSTATE + sg);
        float4 a1 = *(const float4*)(Amat + (e + 1) * DSTATE + sg);
        float4 a2 = *(const float4*)(Amat + (e + 2) * DSTATE + sg);
        float4 a3 = *(const float4*)(Amat + (e + 3) * DSTATE + sg);
        acc.x += xv.x * a0.x + xv.y * a1.x + xv.z * a2.x + xv.w * a3.x;
        acc.y += xv.x * a0.y + xv.y * a1.y + xv.z * a2.y + xv.w * a3.y;
        acc.z += xv.x * a0.z + xv.y * a1.z + xv.z * a2.z + xv.w * a3.z;
        acc.w += xv.x * a0.w + xv.y * a1.w + xv.z * a2.w + xv.w * a3.w;
    }
    *(float4*)(u + (size_t)m * DSTATE + sg) = acc;
}

// ============================================================
// Sequential scan: h_t = tanh(u_t + h_{t-1}).
// 64 independent chains (batch x d_state), one thread each.
// ============================================================
__global__ void scan_kernel(const float* __restrict__ u, float* __restrict__ h)
{
    const int b = threadIdx.x >> 4;
    const int s = threadIdx.x & 15;
    const float* up = u + (size_t)b * LSEQ * DSTATE + s;
    float* hp = h + (size_t)b * LSEQ * DSTATE + s;
    float hv = 0.f;
#pragma unroll 4
    for (int l = 0; l < LSEQ; l++) {
        hv = tanhf(up[(size_t)l * DSTATE] + hv);
        hp[(size_t)l * DSTATE] = hv;
    }
}

// ============================================================
// gated[m,e] = sigmoid(z[m,e]) * ( h[m,:] . C[e,:] + Dp[e]*xconv[m,e] )
// block: 16 m-rows x 256 e-cols
// ============================================================
__global__ __launch_bounds__(256) void gated_kernel(
    const float* __restrict__ Cmat, const float* __restrict__ Dp,
    const float* __restrict__ h, float* __restrict__ gated)
{
    __shared__ float C_sh[256][17];
    __shared__ float h_sh[16][16];

    const int tid = threadIdx.x;
    const int e0 = blockIdx.x * 256;
    const int m0 = blockIdx.y * 16;

    // stage C rows for this e-tile (padded, conflict-free)
    {
        const float* crow = Cmat + (size_t)(e0 + tid) * DSTATE;
#pragma unroll
        for (int i = 0; i < DSTATE; i++) C_sh[tid][i] = crow[i];
    }
    // stage h rows (contiguous)
    ((float*)h_sh)[tid] = h[(size_t)m0 * DSTATE + tid];
    __syncthreads();

    const int e = e0 + tid;
    float creg[DSTATE];
#pragma unroll
    for (int i = 0; i < DSTATE; i++) creg[i] = C_sh[tid][i];
    const float dpe = Dp[e];

#pragma unroll
    for (int mi = 0; mi < 16; mi++) {
        const int m = m0 + mi;
        float dot = 0.f;
#pragma unroll
        for (int i = 0; i < DSTATE; i++) dot = fmaf(h_sh[mi][i], creg[i], dot);
        const float z = g_xz[(size_t)m * N1 + EE + e];
        const float xcv = g_xconv[(size_t)m * EE + e];
        const float sig = 1.f / (1.f + __expf(-z));
        gated[(size_t)m * EE + e] = sig * (dot + dpe * xcv);
    }
}

// ============================================================
extern "C" void kernel_launch(void* const* d_in, const int* in_sizes, int n_in,
                              void* d_out, int out_size)
{
    const float* x      = (const float*)d_in[0];
    const float* W_in   = (const float*)d_in[1];
    const float* b_in   = (const float*)d_in[2];
    const float* conv_w = (const float*)d_in[3];
    const float* conv_b = (const float*)d_in[4];
    const float* Amat   = (const float*)d_in[5];
    const float* Cmat   = (const float*)d_in[6];
    const float* Dp     = (const float*)d_in[7];
    const float* W_out  = (const float*)d_in[8];
    const float* b_out  = (const float*)d_in[9];
    float* out = (float*)d_out;

    float* xz    = nullptr; cudaGetSymbolAddress((void**)&xz,    g_xz);
    float* xconv = nullptr; cudaGetSymbolAddress((void**)&xconv, g_xconv);
    float* u     = nullptr; cudaGetSymbolAddress((void**)&u,     g_u);
    float* h     = nullptr; cudaGetSymbolAddress((void**)&h,     g_h);
    float* gated = nullptr; cudaGetSymbolAddress((void**)&gated, g_gated);

    // 1) xz = x @ W_in + b_in     [16384 x 4096]
    {
        dim3 grid(N1 / 128, M_TOTAL / 128);
        sgemm_bias<128, 128, 8, 8, 8><<<grid, 256>>>(x, W_in, b_in, xz,
                                                     M_TOTAL, N1, DM);
    }
    // 2) causal depthwise conv on x_proj half
    conv_kernel<<<(M_TOTAL * EE) / 256, 256>>>(conv_w, conv_b, xconv);

    // 3) u = xconv @ A            [16384 x 16]
    u_kernel<<<M_TOTAL / 64, 256>>>(Amat, u);

    // 4) sequential tanh scan     (64 chains)
    scan_kernel<<<1, BATCH * DSTATE>>>(u, h);

    // 5) gated = sigmoid(z) * (h @ C^T + Dp * xconv)
    {
        dim3 grid(EE / 256, M_TOTAL / 16);
        gated_kernel<<<grid, 256>>>(Cmat, Dp, h, gated);
    }
    // 6) out = gated @ W_out + b_out   [16384 x 1024]
    {
        dim3 grid(DM / 128, M_TOTAL / 128);
        sgemm_bias<128, 128, 8, 8, 8><<<grid, 256>>>(gated, W_out, b_out, out,
                                                     M_TOTAL, DM, EE);
    }
}

// round 5
// speedup vs baseline: 3.1537x; 3.1537x over previous
#include <cuda_runtime.h>
#include <cuda_bf16.h>
#include <cstdint>
#include <math.h>

#define BATCH   4
#define LSEQ    4096
#define M_TOTAL (BATCH * LSEQ)   // 16384
#define DM      1024
#define EE      2048             // E
#define N1      (2 * EE)         // 4096
#define DSTATE  16
#define DCONV   4

#define KP1 (3 * DM)             // 3072  split-K for GEMM1
#define KP2 (3 * EE)             // 6144  split-K for GEMM2

// -------- scratch (device globals: allocation-free rule) --------
__device__ float         g_xz[M_TOTAL * (size_t)N1];     // 256 MB (x_proj | z)
__device__ float         g_xconv[M_TOTAL * (size_t)EE];  // 128 MB
__device__ float         g_u[M_TOTAL * DSTATE];          // 1 MB
__device__ float         g_h[M_TOTAL * DSTATE];          // 1 MB
__device__ __nv_bfloat16 g_xs[M_TOTAL * (size_t)KP1];    // 96 MB  A' for GEMM1
__device__ __nv_bfloat16 g_w1[(size_t)N1 * KP1];         // 24 MB  B' for GEMM1
__device__ __nv_bfloat16 g_gs[M_TOTAL * (size_t)KP2];    // 192 MB A' for GEMM2
__device__ __nv_bfloat16 g_w2[(size_t)DM * KP2];         // 12 MB  B' for GEMM2

// ============================================================
// helpers
// ============================================================
__device__ __forceinline__ uint32_t smem_u32(const void* p) {
    uint32_t a;
    asm("{ .reg .u64 t; cvta.to.shared.u64 t, %1; cvt.u32.u64 %0, t; }"
        : "=r"(a) : "l"(p));
    return a;
}

#define CP_ASYNC_16(dst_u32, src_ptr) \
    asm volatile("cp.async.cg.shared.global [%0], [%1], 16;" \
                 :: "r"(dst_u32), "l"(src_ptr) : "memory")
#define CP_ASYNC_COMMIT() asm volatile("cp.async.commit_group;" ::: "memory")
#define CP_ASYNC_WAIT0()  asm volatile("cp.async.wait_group 0;" ::: "memory")

__device__ __forceinline__ void ldm_x4(uint32_t& r0, uint32_t& r1,
                                       uint32_t& r2, uint32_t& r3, uint32_t addr) {
    asm volatile("ldmatrix.sync.aligned.m8n8.x4.shared.b16 {%0,%1,%2,%3}, [%4];"
                 : "=r"(r0), "=r"(r1), "=r"(r2), "=r"(r3) : "r"(addr));
}
__device__ __forceinline__ void ldm_x2(uint32_t& r0, uint32_t& r1, uint32_t addr) {
    asm volatile("ldmatrix.sync.aligned.m8n8.x2.shared.b16 {%0,%1}, [%2];"
                 : "=r"(r0), "=r"(r1) : "r"(addr));
}
__device__ __forceinline__ void mma_bf16(float* d, const uint32_t* a,
                                         const uint32_t* b) {
    asm volatile(
        "mma.sync.aligned.m16n8k16.row.col.f32.bf16.bf16.f32 "
        "{%0,%1,%2,%3}, {%4,%5,%6,%7}, {%8,%9}, {%0,%1,%2,%3};"
        : "+f"(d[0]), "+f"(d[1]), "+f"(d[2]), "+f"(d[3])
        : "r"(a[0]), "r"(a[1]), "r"(a[2]), "r"(a[3]), "r"(b[0]), "r"(b[1]));
}

// ============================================================
// bf16 mma.sync GEMM: C[M,N] = A[M,KP] @ B[N,KP]^T + bias[N]
// 128x128 CTA tile, BK=32, 8 warps (warp tile 64m x 32n),
// double-buffered cp.async, rows padded to 40 bf16 (conflict-free ldmatrix).
// ============================================================
#define TBM 128
#define TBN 128
#define TBK 32
#define SMST 40   // padded row stride (bf16 elems); 80B

__global__ __launch_bounds__(256) void mm_gemm(
    const __nv_bfloat16* __restrict__ A,
    const __nv_bfloat16* __restrict__ B,
    const float* __restrict__ bias,
    float* __restrict__ C,
    int N, int KP)
{
    __shared__ __nv_bfloat16 As[2][TBM * SMST];
    __shared__ __nv_bfloat16 Bs[2][TBN * SMST];

    const int tid = threadIdx.x;
    const int wid = tid >> 5;
    const int lane = tid & 31;
    const int bm = blockIdx.y * TBM;
    const int bn = blockIdx.x * TBN;

    const int wm = (wid & 1) * 64;   // warp m-offset in tile
    const int wn = (wid >> 1) * 32;  // warp n-offset in tile

    // global load mapping: 512 16B-chunks per tile; thread does 2 (A) + 2 (B)
    const int lrow0 = tid >> 2;           // 0..63
    const int lcol = (tid & 3) * 8;       // 0,8,16,24
    const __nv_bfloat16* Agl = A + (size_t)(bm + lrow0) * KP + lcol;
    const __nv_bfloat16* Agl2 = Agl + (size_t)64 * KP;
    const __nv_bfloat16* Bgl = B + (size_t)(bn + lrow0) * KP + lcol;
    const __nv_bfloat16* Bgl2 = Bgl + (size_t)64 * KP;

    const uint32_t sA[2] = {smem_u32(&As[0][0]), smem_u32(&As[1][0])};
    const uint32_t sB[2] = {smem_u32(&Bs[0][0]), smem_u32(&Bs[1][0])};
    const uint32_t dstA0 = lrow0 * SMST * 2 + lcol * 2;
    const uint32_t dstA1 = (lrow0 + 64) * SMST * 2 + lcol * 2;

    float acc[4][4][4];
#pragma unroll
    for (int i = 0; i < 4; i++)
#pragma unroll
        for (int j = 0; j < 4; j++)
#pragma unroll
            for (int k = 0; k < 4; k++) acc[i][j][k] = 0.f;

    // ldmatrix source offsets (bytes), fixed per thread
    // A: row = wm + mf*16 + (lane&15); col = (lane>>4)*8 (+ks*16)
    const uint32_t aoffs = ((wm + (lane & 15)) * SMST + (lane >> 4) * 8) * 2;
    // B: row = wn + nf*8 + (lane&7); col = ((lane>>3)&1)*8 (+ks*16)
    const uint32_t boffs = ((wn + (lane & 7)) * SMST + ((lane >> 3) & 1) * 8) * 2;

    const int nchunk = KP / TBK;

    // prefetch chunk 0 into buffer 0
    CP_ASYNC_16(sA[0] + dstA0, Agl);
    CP_ASYNC_16(sA[0] + dstA1, Agl2);
    CP_ASYNC_16(sB[0] + dstA0, Bgl);
    CP_ASYNC_16(sB[0] + dstA1, Bgl2);
    CP_ASYNC_COMMIT();

    for (int c = 0; c < nchunk; c++) {
        const int b = c & 1;
        CP_ASYNC_WAIT0();
        __syncthreads();

        if (c + 1 < nchunk) {
            const int nb = b ^ 1;
            const size_t koff = (size_t)(c + 1) * TBK;
            CP_ASYNC_16(sA[nb] + dstA0, Agl + koff);
            CP_ASYNC_16(sA[nb] + dstA1, Agl2 + koff);
            CP_ASYNC_16(sB[nb] + dstA0, Bgl + koff);
            CP_ASYNC_16(sB[nb] + dstA1, Bgl2 + koff);
            CP_ASYNC_COMMIT();
        }

#pragma unroll
        for (int ks = 0; ks < 2; ks++) {
            uint32_t af[4][4], bf[4][2];
#pragma unroll
            for (int mf = 0; mf < 4; mf++)
                ldm_x4(af[mf][0], af[mf][1], af[mf][2], af[mf][3],
                       sA[b] + aoffs + (mf * 16 * SMST + ks * 16) * 2);
#pragma unroll
            for (int nf = 0; nf < 4; nf++)
                ldm_x2(bf[nf][0], bf[nf][1],
                       sB[b] + boffs + (nf * 8 * SMST + ks * 16) * 2);
#pragma unroll
            for (int mf = 0; mf < 4; mf++)
#pragma unroll
                for (int nf = 0; nf < 4; nf++)
                    mma_bf16(acc[mf][nf], af[mf], bf[nf]);
        }
        __syncthreads();
    }

    // epilogue: acc layout: thread holds (r=lane>>2, c=(lane&3)*2) and (+8, +0/1)
    const int erow = bm + wm + (lane >> 2);
    const int ecol = bn + wn + (lane & 3) * 2;
#pragma unroll
    for (int mf = 0; mf < 4; mf++) {
#pragma unroll
        for (int nf = 0; nf < 4; nf++) {
            const int col = ecol + nf * 8;
            const float bx = bias[col], by = bias[col + 1];
            float* C0 = C + (size_t)(erow + mf * 16) * N + col;
            float* C1 = C0 + (size_t)8 * N;
            *(float2*)C0 = make_float2(acc[mf][nf][0] + bx, acc[mf][nf][1] + by);
            *(float2*)C1 = make_float2(acc[mf][nf][2] + bx, acc[mf][nf][3] + by);
        }
    }
}

// ============================================================
// Split x (fp32 [M,DM]) -> A' = [hi | hi | lo] bf16 [M, 3*DM]
// ============================================================
__global__ void split_x_kernel(const float* __restrict__ x,
                               __nv_bfloat16* __restrict__ xs)
{
    const int idx = blockIdx.x * 256 + threadIdx.x;  // over M_TOTAL*DM
    const int m = idx >> 10;
    const int k = idx & 1023;
    const float a = x[idx];
    const __nv_bfloat16 hi = __float2bfloat16(a);
    const float lo = a - __bfloat162float(hi);
    const size_t base = (size_t)m * KP1;
    xs[base + k] = hi;
    xs[base + DM + k] = hi;
    xs[base + 2 * DM + k] = __float2bfloat16(lo);
}

// ============================================================
// Transpose + split weights: W [K, N] fp32 -> B' [N, 3K] bf16 = [hi | lo | hi]
// ============================================================
__global__ __launch_bounds__(256) void wsplit_kernel(
    const float* __restrict__ W, __nv_bfloat16* __restrict__ Wt, int K, int N)
{
    __shared__ float t[32][33];
    const int k0 = blockIdx.y * 32;
    const int n0 = blockIdx.x * 32;
    const int tx = threadIdx.x & 31;
    const int ty = threadIdx.x >> 5;  // 0..7

    for (int i = ty; i < 32; i += 8)
        t[i][tx] = W[(size_t)(k0 + i) * N + n0 + tx];
    __syncthreads();

    for (int i = ty; i < 32; i += 8) {
        const int n = n0 + i;
        const int k = k0 + tx;
        const float a = t[tx][i];
        const __nv_bfloat16 hi = __float2bfloat16(a);
        const float lo = a - __bfloat162float(hi);
        const size_t base = (size_t)n * 3 * K;
        Wt[base + k] = hi;
        Wt[base + K + k] = __float2bfloat16(lo);
        Wt[base + 2 * K + k] = hi;
    }
}

// ============================================================
// Causal depthwise conv1d, k=4 (reads x_proj half of g_xz)
// ============================================================
__global__ void conv_kernel(const float* __restrict__ cw,
                            const float* __restrict__ cb,
                            float* __restrict__ xconv)
{
    const int idx = blockIdx.x * blockDim.x + threadIdx.x;
    const int e = idx & (EE - 1);
    const int m = idx >> 11;
    const int l = m & (LSEQ - 1);

    float acc = cb[e];
    const float w0 = cw[e * 4 + 0];
    const float w1 = cw[e * 4 + 1];
    const float w2 = cw[e * 4 + 2];
    const float w3 = cw[e * 4 + 3];
    if (l >= 3) acc += w0 * g_xz[(size_t)(m - 3) * N1 + e];
    if (l >= 2) acc += w1 * g_xz[(size_t)(m - 2) * N1 + e];
    if (l >= 1) acc += w2 * g_xz[(size_t)(m - 1) * N1 + e];
    acc += w3 * g_xz[(size_t)m * N1 + e];
    xconv[(size_t)m * EE + e] = acc;
}

// ============================================================
// u[m,s] = xconv[m,:] . A[:,s]
// ============================================================
__global__ void u_kernel(const float* __restrict__ Amat, float* __restrict__ u)
{
    const int m = blockIdx.x * 64 + (threadIdx.x >> 2);
    const int sg = (threadIdx.x & 3) * 4;
    const float* xr = g_xconv + (size_t)m * EE;

    float4 acc = make_float4(0.f, 0.f, 0.f, 0.f);
#pragma unroll 4
    for (int e = 0; e < EE; e += 4) {
        float4 xv = *(const float4*)(xr + e);
        float4 a0 = *(const float4*)(Amat + (e + 0) * DSTATE + sg);
        float4 a1 = *(const float4*)(Amat + (e + 1) * DSTATE + sg);
        float4 a2 = *(const float4*)(Amat + (e + 2) * DSTATE + sg);
        float4 a3 = *(const float4*)(Amat + (e + 3) * DSTATE + sg);
        acc.x += xv.x * a0.x + xv.y * a1.x + xv.z * a2.x + xv.w * a3.x;
        acc.y += xv.x * a0.y + xv.y * a1.y + xv.z * a2.y + xv.w * a3.y;
        acc.z += xv.x * a0.z + xv.y * a1.z + xv.z * a2.z + xv.w * a3.z;
        acc.w += xv.x * a0.w + xv.y * a1.w + xv.z * a2.w + xv.w * a3.w;
    }
    *(float4*)(u + (size_t)m * DSTATE + sg) = acc;
}

// ============================================================
// Sequential scan h_t = tanh(u_t + h_{t-1}) with 16-deep prefetch.
// 64 independent chains.
// ============================================================
__global__ void scan_kernel(const float* __restrict__ u, float* __restrict__ h)
{
    const int b = threadIdx.x >> 4;
    const int s = threadIdx.x & 15;
    const float* up = u + (size_t)b * LSEQ * DSTATE + s;
    float* hp = h + (size_t)b * LSEQ * DSTATE + s;

    float buf[16], nxt[16];
#pragma unroll
    for (int i = 0; i < 16; i++) buf[i] = __ldg(up + (size_t)i * DSTATE);

    float hv = 0.f;
    for (int l0 = 0; l0 < LSEQ; l0 += 16) {
        if (l0 + 16 < LSEQ) {
#pragma unroll
            for (int i = 0; i < 16; i++)
                nxt[i] = __ldg(up + (size_t)(l0 + 16 + i) * DSTATE);
        }
#pragma unroll
        for (int i = 0; i < 16; i++) {
            hv = tanhf(buf[i] + hv);
            hp[(size_t)(l0 + i) * DSTATE] = hv;
        }
#pragma unroll
        for (int i = 0; i < 16; i++) buf[i] = nxt[i];
    }
}

// ============================================================
// gated = sigmoid(z) * (h @ C^T + Dp * xconv) -> bf16 split triple
// G'[m] = [hi | hi | lo]  (A' for GEMM2)
// ============================================================
__global__ __launch_bounds__(256) void gated_kernel(
    const float* __restrict__ Cmat, const float* __restrict__ Dp,
    const float* __restrict__ h, __nv_bfloat16* __restrict__ gs)
{
    __shared__ float C_sh[256][17];
    __shared__ float h_sh[16][16];

    const int tid = threadIdx.x;
    const int e0 = blockIdx.x * 256;
    const int m0 = blockIdx.y * 16;

    {
        const float* crow = Cmat + (size_t)(e0 + tid) * DSTATE;
#pragma unroll
        for (int i = 0; i < DSTATE; i++) C_sh[tid][i] = crow[i];
    }
    ((float*)h_sh)[tid] = h[(size_t)m0 * DSTATE + tid];
    __syncthreads();

    const int e = e0 + tid;
    float creg[DSTATE];
#pragma unroll
    for (int i = 0; i < DSTATE; i++) creg[i] = C_sh[tid][i];
    const float dpe = Dp[e];

#pragma unroll
    for (int mi = 0; mi < 16; mi++) {
        const int m = m0 + mi;
        float dot = 0.f;
#pragma unroll
        for (int i = 0; i < DSTATE; i++) dot = fmaf(h_sh[mi][i], creg[i], dot);
        const float z = g_xz[(size_t)m * N1 + EE + e];
        const float xcv = g_xconv[(size_t)m * EE + e];
        const float sig = 1.f / (1.f + __expf(-z));
        const float val = sig * (dot + dpe * xcv);

        const __nv_bfloat16 hi = __float2bfloat16(val);
        const float lo = val - __bfloat162float(hi);
        const size_t base = (size_t)m * KP2;
        gs[base + e] = hi;
        gs[base + EE + e] = hi;
        gs[base + 2 * EE + e] = __float2bfloat16(lo);
    }
}

// ============================================================
extern "C" void kernel_launch(void* const* d_in, const int* in_sizes, int n_in,
                              void* d_out, int out_size)
{
    const float* x      = (const float*)d_in[0];
    const float* W_in   = (const float*)d_in[1];
    const float* b_in   = (const float*)d_in[2];
    const float* conv_w = (const float*)d_in[3];
    const float* conv_b = (const float*)d_in[4];
    const float* Amat   = (const float*)d_in[5];
    const float* Cmat   = (const float*)d_in[6];
    const float* Dp     = (const float*)d_in[7];
    const float* W_out  = (const float*)d_in[8];
    const float* b_out  = (const float*)d_in[9];
    float* out = (float*)d_out;

    float* xz    = nullptr; cudaGetSymbolAddress((void**)&xz,    g_xz);
    float* xconv = nullptr; cudaGetSymbolAddress((void**)&xconv, g_xconv);
    float* u     = nullptr; cudaGetSymbolAddress((void**)&u,     g_u);
    float* h     = nullptr; cudaGetSymbolAddress((void**)&h,     g_h);
    __nv_bfloat16* xs = nullptr; cudaGetSymbolAddress((void**)&xs, g_xs);
    __nv_bfloat16* w1 = nullptr; cudaGetSymbolAddress((void**)&w1, g_w1);
    __nv_bfloat16* gs = nullptr; cudaGetSymbolAddress((void**)&gs, g_gs);
    __nv_bfloat16* w2 = nullptr; cudaGetSymbolAddress((void**)&w2, g_w2);

    // 0) splits
    split_x_kernel<<<(M_TOTAL * DM) / 256, 256>>>(x, xs);
    {
        dim3 g1(N1 / 32, DM / 32);
        wsplit_kernel<<<g1, 256>>>(W_in, w1, DM, N1);
        dim3 g2(DM / 32, EE / 32);
        wsplit_kernel<<<g2, 256>>>(W_out, w2, EE, DM);
    }

    // 1) xz = x @ W_in + b_in  (bf16-split mma.sync GEMM, K' = 3072)
    {
        dim3 grid(N1 / TBN, M_TOTAL / TBM);
        mm_gemm<<<grid, 256>>>(xs, w1, b_in, xz, N1, KP1);
    }

    // 2) causal depthwise conv
    conv_kernel<<<(M_TOTAL * EE) / 256, 256>>>(conv_w, conv_b, xconv);

    // 3) u = xconv @ A
    u_kernel<<<M_TOTAL / 64, 256>>>(Amat, u);

    // 4) sequential tanh scan
    scan_kernel<<<1, BATCH * DSTATE>>>(u, h);

    // 5) gated (writes bf16 split triple directly)
    {
        dim3 grid(EE / 256, M_TOTAL / 16);
        gated_kernel<<<grid, 256>>>(Cmat, Dp, h, gs);
    }

    // 6) out = gated @ W_out + b_out  (K' = 6144)
    {
        dim3 grid(DM / TBN, M_TOTAL / TBM);
        mm_gemm<<<grid, 256>>>(gs, w2, b_out, out, DM, KP2);
    }
}

// round 7
// speedup vs baseline: 3.3773x; 1.0709x over previous
#include <cuda_runtime.h>
#include <cuda_bf16.h>
#include <cstdint>
#include <math.h>

#define BATCH   4
#define LSEQ    4096
#define M_TOTAL (BATCH * LSEQ)   // 16384
#define DM      1024
#define EE      2048             // E
#define N1      (2 * EE)         // 4096
#define DSTATE  16
#define DCONV   4

#define KP1 (3 * DM)             // 3072  split-K for GEMM1
#define KP2 (3 * EE)             // 6144  split-K for GEMM2

// -------- scratch (device globals: allocation-free rule) --------
__device__ float         g_xz[M_TOTAL * (size_t)N1];     // 256 MB (x_proj | z)
__device__ float         g_xconv[M_TOTAL * (size_t)EE];  // 128 MB
__device__ float         g_u[M_TOTAL * DSTATE];          // 1 MB
__device__ float         g_h[M_TOTAL * DSTATE];          // 1 MB
__device__ __nv_bfloat16 g_xs[M_TOTAL * (size_t)KP1];    // 96 MB  A' for GEMM1
__device__ __nv_bfloat16 g_w1[(size_t)N1 * KP1];         // 24 MB  B' for GEMM1
__device__ __nv_bfloat16 g_gs[M_TOTAL * (size_t)KP2];    // 192 MB A' for GEMM2
__device__ __nv_bfloat16 g_w2[(size_t)DM * KP2];         // 12 MB  B' for GEMM2

// ============================================================
// helpers
// ============================================================
__device__ __forceinline__ uint32_t smem_u32(const void* p) {
    uint32_t a;
    asm("{ .reg .u64 t; cvta.to.shared.u64 t, %1; cvt.u32.u64 %0, t; }"
        : "=r"(a) : "l"(p));
    return a;
}

#define CP_ASYNC_16(dst_u32, src_ptr) \
    asm volatile("cp.async.cg.shared.global [%0], [%1], 16;" \
                 :: "r"(dst_u32), "l"(src_ptr) : "memory")
#define CP_ASYNC_COMMIT() asm volatile("cp.async.commit_group;" ::: "memory")
#define CP_ASYNC_WAIT1()  asm volatile("cp.async.wait_group 1;" ::: "memory")

__device__ __forceinline__ void ldm_x4(uint32_t& r0, uint32_t& r1,
                                       uint32_t& r2, uint32_t& r3, uint32_t addr) {
    asm volatile("ldmatrix.sync.aligned.m8n8.x4.shared.b16 {%0,%1,%2,%3}, [%4];"
                 : "=r"(r0), "=r"(r1), "=r"(r2), "=r"(r3) : "r"(addr));
}
__device__ __forceinline__ void ldm_x2(uint32_t& r0, uint32_t& r1, uint32_t addr) {
    asm volatile("ldmatrix.sync.aligned.m8n8.x2.shared.b16 {%0,%1}, [%2];"
                 : "=r"(r0), "=r"(r1) : "r"(addr));
}
__device__ __forceinline__ void mma_bf16(float* d, const uint32_t* a,
                                         const uint32_t* b) {
    asm volatile(
        "mma.sync.aligned.m16n8k16.row.col.f32.bf16.bf16.f32 "
        "{%0,%1,%2,%3}, {%4,%5,%6,%7}, {%8,%9}, {%0,%1,%2,%3};"
        : "+f"(d[0]), "+f"(d[1]), "+f"(d[2]), "+f"(d[3])
        : "r"(a[0]), "r"(a[1]), "r"(a[2]), "r"(a[3]), "r"(b[0]), "r"(b[1]));
}

// ============================================================
// bf16 mma.sync GEMM: C[M,N] = A[M,KP] @ B[N,KP]^T + bias[N]
// 128x128 CTA tile, BK=32, 8 warps (warp tile 64m x 32n),
// 3-stage cp.async pipeline (wait_group 1), padded rows (SMST=40)
// for conflict-free ldmatrix.
// ============================================================
#define TBM 128
#define TBN 128
#define TBK 32
#define SMST 40                 // padded row stride (bf16 elems); 80B
#define STAGE_A_BYTES (TBM * SMST * 2)              // 10240
#define STAGE_BYTES   (2 * STAGE_A_BYTES)           // 20480 (A then B)
#define NSTAGE 3
#define MM_SMEM_BYTES (NSTAGE * STAGE_BYTES)        // 61440

__global__ __launch_bounds__(256, 2) void mm_gemm(
    const __nv_bfloat16* __restrict__ A,
    const __nv_bfloat16* __restrict__ B,
    const float* __restrict__ bias,
    float* __restrict__ C,
    int N, int KP)
{
    extern __shared__ char dynsmem[];
    const uint32_t sbase = smem_u32(dynsmem);

    const int tid = threadIdx.x;
    const int wid = tid >> 5;
    const int lane = tid & 31;
    const int bm = blockIdx.y * TBM;
    const int bn = blockIdx.x * TBN;

    const int wm = (wid & 1) * 64;   // warp m-offset in tile
    const int wn = (wid >> 1) * 32;  // warp n-offset in tile

    // global load mapping: thread does 2 (A) + 2 (B) 16B chunks per stage
    const int lrow0 = tid >> 2;           // 0..63
    const int lcol = (tid & 3) * 8;       // 0,8,16,24
    const __nv_bfloat16* Agl = A + (size_t)(bm + lrow0) * KP + lcol;
    const __nv_bfloat16* Agl2 = Agl + (size_t)64 * KP;
    const __nv_bfloat16* Bgl = B + (size_t)(bn + lrow0) * KP + lcol;
    const __nv_bfloat16* Bgl2 = Bgl + (size_t)64 * KP;

    uint32_t sA[NSTAGE], sB[NSTAGE];
#pragma unroll
    for (int s = 0; s < NSTAGE; s++) {
        sA[s] = sbase + s * STAGE_BYTES;
        sB[s] = sA[s] + STAGE_A_BYTES;
    }
    const uint32_t dst0 = lrow0 * SMST * 2 + lcol * 2;
    const uint32_t dst1 = (lrow0 + 64) * SMST * 2 + lcol * 2;

    float acc[4][4][4];
#pragma unroll
    for (int i = 0; i < 4; i++)
#pragma unroll
        for (int j = 0; j < 4; j++)
#pragma unroll
            for (int k = 0; k < 4; k++) acc[i][j][k] = 0.f;

    // ldmatrix source offsets (bytes), fixed per thread
    const uint32_t aoffs = ((wm + (lane & 15)) * SMST + (lane >> 4) * 8) * 2;
    const uint32_t boffs = ((wn + (lane & 7)) * SMST + ((lane >> 3) & 1) * 8) * 2;

    const int nchunk = KP / TBK;     // >= 96

    // prologue: prefetch stages 0..NSTAGE-2
#pragma unroll
    for (int s = 0; s < NSTAGE - 1; s++) {
        const size_t koff = (size_t)s * TBK;
        CP_ASYNC_16(sA[s] + dst0, Agl + koff);
        CP_ASYNC_16(sA[s] + dst1, Agl2 + koff);
        CP_ASYNC_16(sB[s] + dst0, Bgl + koff);
        CP_ASYNC_16(sB[s] + dst1, Bgl2 + koff);
        CP_ASYNC_COMMIT();
    }

    int buf = 0, nbuf = NSTAGE - 1;
    for (int c = 0; c < nchunk; c++) {
        CP_ASYNC_WAIT1();            // oldest group (chunk c) landed
        __syncthreads();

        // issue chunk c + NSTAGE-1 into nbuf (its old contents were
        // consumed at iteration c-1; the sync above covers all warps)
        if (c + NSTAGE - 1 < nchunk) {
            const size_t koff = (size_t)(c + NSTAGE - 1) * TBK;
            CP_ASYNC_16(sA[nbuf] + dst0, Agl + koff);
            CP_ASYNC_16(sA[nbuf] + dst1, Agl2 + koff);
            CP_ASYNC_16(sB[nbuf] + dst0, Bgl + koff);
            CP_ASYNC_16(sB[nbuf] + dst1, Bgl2 + koff);
        }
        CP_ASYNC_COMMIT();           // commit every iter (empty at tail) to
                                     // keep wait_group accounting exact

#pragma unroll
        for (int ks = 0; ks < 2; ks++) {
            uint32_t af[4][4], bfr[4][2];
#pragma unroll
            for (int mf = 0; mf < 4; mf++)
                ldm_x4(af[mf][0], af[mf][1], af[mf][2], af[mf][3],
                       sA[buf] + aoffs + (mf * 16 * SMST + ks * 16) * 2);
#pragma unroll
            for (int nf = 0; nf < 4; nf++)
                ldm_x2(bfr[nf][0], bfr[nf][1],
                       sB[buf] + boffs + (nf * 8 * SMST + ks * 16) * 2);
#pragma unroll
            for (int mf = 0; mf < 4; mf++)
#pragma unroll
                for (int nf = 0; nf < 4; nf++)
                    mma_bf16(acc[mf][nf], af[mf], bfr[nf]);
        }

        buf = (buf + 1 == NSTAGE) ? 0 : buf + 1;
        nbuf = (nbuf + 1 == NSTAGE) ? 0 : nbuf + 1;
    }

    // epilogue
    const int erow = bm + wm + (lane >> 2);
    const int ecol = bn + wn + (lane & 3) * 2;
#pragma unroll
    for (int mf = 0; mf < 4; mf++) {
#pragma unroll
        for (int nf = 0; nf < 4; nf++) {
            const int col = ecol + nf * 8;
            const float bx = bias[col], by = bias[col + 1];
            float* C0 = C + (size_t)(erow + mf * 16) * N + col;
            float* C1 = C0 + (size_t)8 * N;
            *(float2*)C0 = make_float2(acc[mf][nf][0] + bx, acc[mf][nf][1] + by);
            *(float2*)C1 = make_float2(acc[mf][nf][2] + bx, acc[mf][nf][3] + by);
        }
    }
}

// ============================================================
// Split x (fp32 [M,DM]) -> A' = [hi | hi | lo] bf16 [M, 3*DM]
// ============================================================
__global__ void split_x_kernel(const float* __restrict__ x,
                               __nv_bfloat16* __restrict__ xs)
{
    const int idx = blockIdx.x * 256 + threadIdx.x;  // over M_TOTAL*DM
    const int m = idx >> 10;
    const int k = idx & 1023;
    const float a = x[idx];
    const __nv_bfloat16 hi = __float2bfloat16(a);
    const float lo = a - __bfloat162float(hi);
    const size_t base = (size_t)m * KP1;
    xs[base + k] = hi;
    xs[base + DM + k] = hi;
    xs[base + 2 * DM + k] = __float2bfloat16(lo);
}

// ============================================================
// Transpose + split weights: W [K, N] fp32 -> B' [N, 3K] bf16 = [hi | lo | hi]
// ============================================================
__global__ __launch_bounds__(256) void wsplit_kernel(
    const float* __restrict__ W, __nv_bfloat16* __restrict__ Wt, int K, int N)
{
    __shared__ float t[32][33];
    const int k0 = blockIdx.y * 32;
    const int n0 = blockIdx.x * 32;
    const int tx = threadIdx.x & 31;
    const int ty = threadIdx.x >> 5;  // 0..7

    for (int i = ty; i < 32; i += 8)
        t[i][tx] = W[(size_t)(k0 + i) * N + n0 + tx];
    __syncthreads();

    for (int i = ty; i < 32; i += 8) {
        const int n = n0 + i;
        const int k = k0 + tx;
        const float a = t[tx][i];
        const __nv_bfloat16 hi = __float2bfloat16(a);
        const float lo = a - __bfloat162float(hi);
        const size_t base = (size_t)n * 3 * K;
        Wt[base + k] = hi;
        Wt[base + K + k] = __float2bfloat16(lo);
        Wt[base + 2 * K + k] = hi;
    }
}

// ============================================================
// Causal depthwise conv1d, k=4 (reads x_proj half of g_xz)
// ============================================================
__global__ void conv_kernel(const float* __restrict__ cw,
                            const float* __restrict__ cb,
                            float* __restrict__ xconv)
{
    const int idx = blockIdx.x * blockDim.x + threadIdx.x;
    const int e = idx & (EE - 1);
    const int m = idx >> 11;
    const int l = m & (LSEQ - 1);

    float acc = cb[e];
    const float w0 = cw[e * 4 + 0];
    const float w1 = cw[e * 4 + 1];
    const float w2 = cw[e * 4 + 2];
    const float w3 = cw[e * 4 + 3];
    if (l >= 3) acc += w0 * g_xz[(size_t)(m - 3) * N1 + e];
    if (l >= 2) acc += w1 * g_xz[(size_t)(m - 2) * N1 + e];
    if (l >= 1) acc += w2 * g_xz[(size_t)(m - 1) * N1 + e];
    acc += w3 * g_xz[(size_t)m * N1 + e];
    xconv[(size_t)m * EE + e] = acc;
}

// ============================================================
// u[m,s] = xconv[m,:] . A[:,s]
// ============================================================
__global__ void u_kernel(const float* __restrict__ Amat, float* __restrict__ u)
{
    const int m = blockIdx.x * 64 + (threadIdx.x >> 2);
    const int sg = (threadIdx.x & 3) * 4;
    const float* xr = g_xconv + (size_t)m * EE;

    float4 acc = make_float4(0.f, 0.f, 0.f, 0.f);
#pragma unroll 4
    for (int e = 0; e < EE; e += 4) {
        float4 xv = *(const float4*)(xr + e);
        float4 a0 = *(const float4*)(Amat + (e + 0) * DSTATE + sg);
        float4 a1 = *(const float4*)(Amat + (e + 1) * DSTATE + sg);
        float4 a2 = *(const float4*)(Amat + (e + 2) * DSTATE + sg);
        float4 a3 = *(const float4*)(Amat + (e + 3) * DSTATE + sg);
        acc.x += xv.x * a0.x + xv.y * a1.x + xv.z * a2.x + xv.w * a3.x;
        acc.y += xv.x * a0.y + xv.y * a1.y + xv.z * a2.y + xv.w * a3.y;
        acc.z += xv.x * a0.z + xv.y * a1.z + xv.z * a2.z + xv.w * a3.z;
        acc.w += xv.x * a0.w + xv.y * a1.w + xv.z * a2.w + xv.w * a3.w;
    }
    *(float4*)(u + (size_t)m * DSTATE + sg) = acc;
}

// ============================================================
// Sequential scan h_t = tanh(u_t + h_{t-1}), hardware tanh.approx,
// 16-deep load prefetch. 64 independent chains.
// ============================================================
__global__ void scan_kernel(const float* __restrict__ u, float* __restrict__ h)
{
    const int b = threadIdx.x >> 4;
    const int s = threadIdx.x & 15;
    const float* up = u + (size_t)b * LSEQ * DSTATE + s;
    float* hp = h + (size_t)b * LSEQ * DSTATE + s;

    float buf[16], nxt[16];
#pragma unroll
    for (int i = 0; i < 16; i++) buf[i] = __ldg(up + (size_t)i * DSTATE);

    float hv = 0.f;
    for (int l0 = 0; l0 < LSEQ; l0 += 16) {
        if (l0 + 16 < LSEQ) {
#pragma unroll
            for (int i = 0; i < 16; i++)
                nxt[i] = __ldg(up + (size_t)(l0 + 16 + i) * DSTATE);
        }
#pragma unroll
        for (int i = 0; i < 16; i++) {
            hv += buf[i];
            asm("tanh.approx.f32 %0, %0;" : "+f"(hv));
            hp[(size_t)(l0 + i) * DSTATE] = hv;
        }
#pragma unroll
        for (int i = 0; i < 16; i++) buf[i] = nxt[i];
    }
}

// ============================================================
// gated = sigmoid(z) * (h @ C^T + Dp * xconv) -> bf16 split triple
// G'[m] = [hi | hi | lo]  (A' for GEMM2)
// ============================================================
__global__ __launch_bounds__(256) void gated_kernel(
    const float* __restrict__ Cmat, const float* __restrict__ Dp,
    const float* __restrict__ h, __nv_bfloat16* __restrict__ gs)
{
    __shared__ float C_sh[256][17];
    __shared__ float h_sh[16][16];

    const int tid = threadIdx.x;
    const int e0 = blockIdx.x * 256;
    const int m0 = blockIdx.y * 16;

    {
        const float* crow = Cmat + (size_t)(e0 + tid) * DSTATE;
#pragma unroll
        for (int i = 0; i < DSTATE; i++) C_sh[tid][i] = crow[i];
    }
    ((float*)h_sh)[tid] = h[(size_t)m0 * DSTATE + tid];
    __syncthreads();

    const int e = e0 + tid;
    float creg[DSTATE];
#pragma unroll
    for (int i = 0; i < DSTATE; i++) creg[i] = C_sh[tid][i];
    const float dpe = Dp[e];

#pragma unroll
    for (int mi = 0; mi < 16; mi++) {
        const int m = m0 + mi;
        float dot = 0.f;
#pragma unroll
        for (int i = 0; i < DSTATE; i++) dot = fmaf(h_sh[mi][i], creg[i], dot);
        const float z = g_xz[(size_t)m * N1 + EE + e];
        const float xcv = g_xconv[(size_t)m * EE + e];
        const float sig = 1.f / (1.f + __expf(-z));
        const float val = sig * (dot + dpe * xcv);

        const __nv_bfloat16 hi = __float2bfloat16(val);
        const float lo = val - __bfloat162float(hi);
        const size_t base = (size_t)m * KP2;
        gs[base + e] = hi;
        gs[base + EE + e] = hi;
        gs[base + 2 * EE + e] = __float2bfloat16(lo);
    }
}

// ============================================================
extern "C" void kernel_launch(void* const* d_in, const int* in_sizes, int n_in,
                              void* d_out, int out_size)
{
    const float* x      = (const float*)d_in[0];
    const float* W_in   = (const float*)d_in[1];
    const float* b_in   = (const float*)d_in[2];
    const float* conv_w = (const float*)d_in[3];
    const float* conv_b = (const float*)d_in[4];
    const float* Amat   = (const float*)d_in[5];
    const float* Cmat   = (const float*)d_in[6];
    const float* Dp     = (const float*)d_in[7];
    const float* W_out  = (const float*)d_in[8];
    const float* b_out  = (const float*)d_in[9];
    float* out = (float*)d_out;

    float* xz    = nullptr; cudaGetSymbolAddress((void**)&xz,    g_xz);
    float* xconv = nullptr; cudaGetSymbolAddress((void**)&xconv, g_xconv);
    float* u     = nullptr; cudaGetSymbolAddress((void**)&u,     g_u);
    float* h     = nullptr; cudaGetSymbolAddress((void**)&h,     g_h);
    __nv_bfloat16* xs = nullptr; cudaGetSymbolAddress((void**)&xs, g_xs);
    __nv_bfloat16* w1 = nullptr; cudaGetSymbolAddress((void**)&w1, g_w1);
    __nv_bfloat16* gs = nullptr; cudaGetSymbolAddress((void**)&gs, g_gs);
    __nv_bfloat16* w2 = nullptr; cudaGetSymbolAddress((void**)&w2, g_w2);

    cudaFuncSetAttribute(mm_gemm, cudaFuncAttributeMaxDynamicSharedMemorySize,
                         MM_SMEM_BYTES);

    // 0) splits
    split_x_kernel<<<(M_TOTAL * DM) / 256, 256>>>(x, xs);
    {
        dim3 g1(N1 / 32, DM / 32);
        wsplit_kernel<<<g1, 256>>>(W_in, w1, DM, N1);
        dim3 g2(DM / 32, EE / 32);
        wsplit_kernel<<<g2, 256>>>(W_out, w2, EE, DM);
    }

    // 1) xz = x @ W_in + b_in  (bf16-split mma.sync GEMM, K' = 3072)
    {
        dim3 grid(N1 / TBN, M_TOTAL / TBM);
        mm_gemm<<<grid, 256, MM_SMEM_BYTES>>>(xs, w1, b_in, xz, N1, KP1);
    }

    // 2) causal depthwise conv
    conv_kernel<<<(M_TOTAL * EE) / 256, 256>>>(conv_w, conv_b, xconv);

    // 3) u = xconv @ A
    u_kernel<<<M_TOTAL / 64, 256>>>(Amat, u);

    // 4) sequential tanh scan
    scan_kernel<<<1, BATCH * DSTATE>>>(u, h);

    // 5) gated (writes bf16 split triple directly)
    {
        dim3 grid(EE / 256, M_TOTAL / 16);
        gated_kernel<<<grid, 256>>>(Cmat, Dp, h, gs);
    }

    // 6) out = gated @ W_out + b_out  (K' = 6144)
    {
        dim3 grid(DM / TBN, M_TOTAL / TBM);
        mm_gemm<<<grid, 256, MM_SMEM_BYTES>>>(gs, w2, b_out, out, DM, KP2);
    }
}